// round 15
// baseline (speedup 1.0000x reference)
#include <cuda_runtime.h>
#include <cuda_fp16.h>
#include <math.h>
#include <stdint.h>

#define BATCH 2
#define SEQ 2048
#define DMODEL 1024
#define NH 16
#define DH 64
#define MTOT (BATCH*SEQ)
#define BH (BATCH*NH)

// ---------------------------------------------------------------------------
// Device global scratch
// ---------------------------------------------------------------------------
__device__ float g_cos[SEQ*32];
__device__ float g_sin[SEQ*32];
__device__ __align__(128) __half g_Xcat[(size_t)MTOT*2048];
__device__ __align__(128) __half g_Acat[(size_t)MTOT*2048];
__device__ __align__(128) __half g_Wq16[1024*1024];
__device__ __align__(128) __half g_Wk16[1024*1024];
__device__ __align__(128) __half g_Wv16[1024*1024];
__device__ __align__(128) __half g_Wo16[1024*1024];
__device__ __align__(128) __half g_Qc[(size_t)BH*SEQ*128];
__device__ __align__(128) __half g_Kc[(size_t)BH*SEQ*64];
__device__ __align__(128) __half g_Vc[(size_t)BH*SEQ*64];

__device__ __forceinline__ uint32_t smem_u32(const void* p) {
    uint32_t a;
    asm("{ .reg .u64 t; cvta.to.shared.u64 t, %1; cvt.u32.u64 %0, t; }"
        : "=r"(a) : "l"(p));
    return a;
}
#define CP_ASYNC16(dst, src) \
    asm volatile("cp.async.cg.shared.global [%0], [%1], 16;" \
                 :: "r"(dst), "l"(src) : "memory")
#define CP_COMMIT() asm volatile("cp.async.commit_group;" ::: "memory")
#define CP_WAIT0()  asm volatile("cp.async.wait_group 0;" ::: "memory")
#define CP_WAIT2()  asm volatile("cp.async.wait_group 2;" ::: "memory")
#define LDM_X4(r0, r1, r2, r3, addr) \
    asm volatile("ldmatrix.sync.aligned.m8n8.x4.shared.b16 {%0,%1,%2,%3}, [%4];" \
                 : "=r"(r0), "=r"(r1), "=r"(r2), "=r"(r3) : "r"(addr))
#define LDM_X4_T(r0, r1, r2, r3, addr) \
    asm volatile("ldmatrix.sync.aligned.m8n8.x4.trans.shared.b16 {%0,%1,%2,%3}, [%4];" \
                 : "=r"(r0), "=r"(r1), "=r"(r2), "=r"(r3) : "r"(addr))
#define MMA16816(c, a, b) \
    asm volatile("mma.sync.aligned.m16n8k16.row.col.f32.f16.f16.f32 " \
                 "{%0,%1,%2,%3}, {%4,%5,%6,%7}, {%8,%9}, {%0,%1,%2,%3};" \
                 : "+f"((c)[0]), "+f"((c)[1]), "+f"((c)[2]), "+f"((c)[3]) \
                 : "r"((a)[0]), "r"((a)[1]), "r"((a)[2]), "r"((a)[3]), \
                   "r"((b)[0]), "r"((b)[1]))

__device__ __forceinline__ uint32_t packh(float a, float b) {
    uint32_t r;
    asm("cvt.rn.f16x2.f32 %0, %2, %1;" : "=r"(r) : "f"(a), "f"(b));
    return r;
}

// ---------------------------------------------------------------------------
// RoPE table
// ---------------------------------------------------------------------------
__global__ void rope_table_kernel()
{
    int idx = blockIdx.x * blockDim.x + threadIdx.x;
    if (idx >= SEQ * 32) return;
    int p = idx & 31;
    int s = idx >> 5;
    double inv = pow(10000.0, -(double)p / 32.0);
    double sd, cd;
    sincos((double)s * inv, &sd, &cd);
    g_cos[idx] = (float)cd;
    g_sin[idx] = (float)sd;
}

// ---------------------------------------------------------------------------
// fp32 -> fp16 hi/lo split (x)
// ---------------------------------------------------------------------------
__global__ void split_kernel(const float* __restrict__ src,
                             __half* __restrict__ dst, int n4)
{
    int i = blockIdx.x * blockDim.x + threadIdx.x;
    if (i >= n4) return;
    int row = i >> 8;
    int kq = (i & 255) << 2;
    float4 v = *(const float4*)&src[(size_t)row * 1024 + kq];
    float vv[4] = {v.x, v.y, v.z, v.w};
    ushort4 hp, lp;
    unsigned short* h = (unsigned short*)&hp;
    unsigned short* l = (unsigned short*)&lp;
#pragma unroll
    for (int q = 0; q < 4; q++) {
        __half hh = __float2half_rn(vv[q]);
        h[q] = *(unsigned short*)&hh;
        __half ll = __float2half_rn(vv[q] - __half2float(hh));
        l[q] = *(unsigned short*)&ll;
    }
    size_t rb = (size_t)row * 2048;
    *(ushort4*)&dst[rb + kq] = hp;
    *(ushort4*)&dst[rb + 1024 + kq] = lp;
}

// ---------------------------------------------------------------------------
// fp32 -> fp16 convert, all 4 weights in one launch
// ---------------------------------------------------------------------------
__global__ void w16all_kernel(const float* __restrict__ s0, const float* __restrict__ s1,
                              const float* __restrict__ s2, const float* __restrict__ s3,
                              __half* __restrict__ d0, __half* __restrict__ d1,
                              __half* __restrict__ d2, __half* __restrict__ d3)
{
    int i = blockIdx.x * blockDim.x + threadIdx.x;
    if (i >= 1024 * 256) return;
    const float* s; __half* d;
    switch (blockIdx.y) {
        case 0: s = s0; d = d0; break;
        case 1: s = s1; d = d1; break;
        case 2: s = s2; d = d2; break;
        default: s = s3; d = d3; break;
    }
    float4 v = *(const float4*)&s[(size_t)i * 4];
    ushort4 hp;
    unsigned short* h = (unsigned short*)&hp;
    __half h0 = __float2half_rn(v.x); h[0] = *(unsigned short*)&h0;
    __half h1 = __float2half_rn(v.y); h[1] = *(unsigned short*)&h1;
    __half h2 = __float2half_rn(v.z); h[2] = *(unsigned short*)&h2;
    __half h3 = __float2half_rn(v.w); h[3] = *(unsigned short*)&h3;
    *(ushort4*)&d[(size_t)i * 4] = hp;
}

// ---------------------------------------------------------------------------
// HMMA fp16 2-term GEMM, fused hi+lo per W-chunk (R14, unchanged).
// ---------------------------------------------------------------------------
#define ALO_OFF 8192
#define W_OFF 16384
#define STG4 32768
#define GSMEM (2*STG4)
#define NCH4 16

template<int QKV>
__global__ __launch_bounds__(256, 3)
void hmma_gemm(const __half* __restrict__ A,
               const __half* __restrict__ W0,
               const __half* __restrict__ W1,
               const __half* __restrict__ W2,
               float* __restrict__ Y0, float* __restrict__ Y1,
               float* __restrict__ Y2)
{
    extern __shared__ char smem[];
    const uint32_t sb = smem_u32(smem);
    const int tid = threadIdx.x;
    const int lane = tid & 31;
    const int w = tid >> 5;
    const int wm = w & 1, wn = w >> 1;

    const int m0 = blockIdx.x * 64;
    const int by = blockIdx.y;
    const int ws = QKV ? (by >> 3) : 0;
    const int nblk = by & 7;

    const __half* W = W0;
    float* Y = Y0;
    if (QKV) {
        if (ws == 1) { W = W1; Y = Y1; }
        else if (ws == 2) { W = W2; Y = Y2; }
    }

    uint32_t dA[2]; const __half* sA[2];
#pragma unroll
    for (int i = 0; i < 2; i++) {
        int u = tid + i * 256;
        int r = u >> 3, c16 = u & 7;
        dA[i] = sb + r * 128 + ((c16 ^ (r & 7)) * 16);
        sA[i] = A + (size_t)(m0 + r) * 2048 + c16 * 8;
    }
    uint32_t dW[4]; const __half* sW[4];
#pragma unroll
    for (int i = 0; i < 4; i++) {
        int u = tid + i * 256;
        int r = u >> 3, c16 = u & 7;
        dW[i] = sb + W_OFF + r * 128 + ((c16 ^ (r & 7)) * 16);
        sW[i] = W + (size_t)(nblk * 128 + r) * 1024 + c16 * 8;
    }

    float c[2][4][4];
#pragma unroll
    for (int i = 0; i < 2; i++)
#pragma unroll
        for (int j = 0; j < 4; j++)
#pragma unroll
            for (int q = 0; q < 4; q++) c[i][j][q] = 0.f;

    {
#pragma unroll
        for (int i = 0; i < 2; i++) {
            CP_ASYNC16(dA[i], sA[i]);
            CP_ASYNC16(dA[i] + ALO_OFF, sA[i] + 1024);
        }
#pragma unroll
        for (int i = 0; i < 4; i++) CP_ASYNC16(dW[i], sW[i]);
        CP_COMMIT();
    }

    const int arow = wm * 32 + (lane & 15);
    const uint32_t axor = (uint32_t)(arow & 7) << 4;
    const uint32_t aBase = sb + arow * 128;
    const uint32_t acol0 = ((uint32_t)(lane >> 4)) * 16;
    const int brow = wn * 32 + ((lane >> 4) & 1) * 8 + (lane & 7);
    const uint32_t bxor = (uint32_t)(brow & 7) << 4;
    const uint32_t bBase = sb + W_OFF + brow * 128;
    const uint32_t bcol0 = ((uint32_t)((lane >> 3) & 1)) * 16;

    for (int cc = 0; cc < NCH4; cc++) {
        CP_WAIT0();
        __syncthreads();
        if (cc + 1 < NCH4) {
            uint32_t so = ((cc + 1) & 1) * STG4;
            int k = (cc + 1) * 64;
#pragma unroll
            for (int i = 0; i < 2; i++) {
                CP_ASYNC16(dA[i] + so, sA[i] + k);
                CP_ASYNC16(dA[i] + ALO_OFF + so, sA[i] + k + 1024);
            }
#pragma unroll
            for (int i = 0; i < 4; i++) CP_ASYNC16(dW[i] + so, sW[i] + k);
            CP_COMMIT();
        }

        const uint32_t so = (cc & 1) * STG4;
#pragma unroll
        for (int kh = 0; kh < 4; kh++) {
            uint32_t ah[2][4], al[2][4], b[4][2];
#pragma unroll
            for (int mt = 0; mt < 2; mt++) {
                uint32_t off = mt * 2048 + ((kh * 32 + acol0) ^ axor);
                LDM_X4(ah[mt][0], ah[mt][1], ah[mt][2], ah[mt][3],
                       aBase + so + off);
                LDM_X4(al[mt][0], al[mt][1], al[mt][2], al[mt][3],
                       aBase + ALO_OFF + so + off);
            }
#pragma unroll
            for (int p = 0; p < 2; p++)
                LDM_X4(b[2*p][0], b[2*p][1], b[2*p+1][0], b[2*p+1][1],
                       bBase + so + p * 2048 + ((kh * 32 + bcol0) ^ bxor));
#pragma unroll
            for (int mt = 0; mt < 2; mt++)
#pragma unroll
                for (int nt = 0; nt < 4; nt++) {
                    MMA16816(c[mt][nt], ah[mt], b[nt]);
                    MMA16816(c[mt][nt], al[mt], b[nt]);
                }
        }
    }

    if (QKV && ws == 2) {
#pragma unroll
        for (int mt = 0; mt < 2; mt++) {
            int mrow = m0 + wm * 32 + mt * 16 + (lane >> 2);
#pragma unroll
            for (int nt = 0; nt < 4; nt++) {
                int n = nblk * 128 + wn * 32 + nt * 8 + (lane & 3) * 2;
                int h = n >> 6, d0 = n & 63;
                int b = mrow >> 11, s = mrow & (SEQ - 1);
                __half* dst = (__half*)Y +
                    (((size_t)((b << 4) + h) * SEQ + s) * 64 + d0);
                *(uint32_t*)dst = packh(c[mt][nt][0], c[mt][nt][1]);
                *(uint32_t*)(dst + 8 * 64) = packh(c[mt][nt][2], c[mt][nt][3]);
            }
        }
    } else if (QKV) {
        __syncthreads();
        float* ot = (float*)smem;
        {
#pragma unroll
            for (int mt = 0; mt < 2; mt++) {
                int ml = wm * 32 + mt * 16 + (lane >> 2);
#pragma unroll
                for (int nt = 0; nt < 4; nt++) {
                    int n = wn * 32 + nt * 8 + (lane & 3) * 2;
                    ot[ml * 132 + n]     = c[mt][nt][0];
                    ot[ml * 132 + n + 1] = c[mt][nt][1];
                    ot[(ml + 8) * 132 + n]     = c[mt][nt][2];
                    ot[(ml + 8) * 132 + n + 1] = c[mt][nt][3];
                }
            }
        }
        __syncthreads();
        {
            const int dq = (tid & 7) * 4;
            const float qs = (ws == 0) ? 0.125f : 1.f;
#pragma unroll
            for (int rp = 0; rp < 2; rp++) {
                int ml = (tid >> 3) + rp * 32;
                int mrow = m0 + ml;
                int b = mrow >> 11, s = mrow & (SEQ - 1);
                float4 cs4 = *(const float4*)&g_cos[s * 32 + dq];
                float4 sn4 = *(const float4*)&g_sin[s * 32 + dq];
                float csv[4] = {cs4.x, cs4.y, cs4.z, cs4.w};
                float snv[4] = {sn4.x, sn4.y, sn4.z, sn4.w};
#pragma unroll
                for (int hh2 = 0; hh2 < 2; hh2++) {
                    int h = nblk * 2 + hh2;
                    float r1[4], r2[4];
#pragma unroll
                    for (int i = 0; i < 4; i++) {
                        float v1 = ot[ml * 132 + hh2 * 64 + dq + i];
                        float v2 = ot[ml * 132 + hh2 * 64 + dq + 32 + i];
                        r1[i] = (v1 * csv[i] - v2 * snv[i]) * qs;
                        r2[i] = (v2 * csv[i] + v1 * snv[i]) * qs;
                    }
                    if (ws == 0) {
                        __half* qd = (__half*)Y + ((size_t)((b << 4) + h) * SEQ + s) * 128;
                        uint32_t h0 = packh(r1[0], r1[1]), h1p = packh(r1[2], r1[3]);
                        __half2 a0 = *(__half2*)&h0, a1 = *(__half2*)&h1p;
                        uint32_t l0 = packh(r1[0] - __low2float(a0), r1[1] - __high2float(a0));
                        uint32_t l1 = packh(r1[2] - __low2float(a1), r1[3] - __high2float(a1));
                        *(uint2*)(qd + dq)      = make_uint2(h0, h1p);
                        *(uint2*)(qd + 64 + dq) = make_uint2(l0, l1);
                        uint32_t h2v = packh(r2[0], r2[1]), h3v = packh(r2[2], r2[3]);
                        __half2 b0 = *(__half2*)&h2v, b1 = *(__half2*)&h3v;
                        uint32_t l2 = packh(r2[0] - __low2float(b0), r2[1] - __high2float(b0));
                        uint32_t l3 = packh(r2[2] - __low2float(b1), r2[3] - __high2float(b1));
                        *(uint2*)(qd + dq + 32)      = make_uint2(h2v, h3v);
                        *(uint2*)(qd + 64 + dq + 32) = make_uint2(l2, l3);
                    } else {
                        __half* kd = (__half*)Y + ((size_t)((b << 4) + h) * SEQ + s) * 64;
                        *(uint2*)(kd + dq)      = make_uint2(packh(r1[0], r1[1]), packh(r1[2], r1[3]));
                        *(uint2*)(kd + dq + 32) = make_uint2(packh(r2[0], r2[1]), packh(r2[2], r2[3]));
                    }
                }
            }
        }
    } else {
#pragma unroll
        for (int mt = 0; mt < 2; mt++) {
            int mrow = m0 + wm * 32 + mt * 16 + (lane >> 2);
#pragma unroll
            for (int nt = 0; nt < 4; nt++) {
                int n = nblk * 128 + wn * 32 + nt * 8 + (lane & 3) * 2;
                float* dst = Y + (size_t)mrow * 1024 + n;
                *(float2*)dst = make_float2(c[mt][nt][0], c[mt][nt][1]);
                *(float2*)(dst + 8 * 1024) = make_float2(c[mt][nt][2], c[mt][nt][3]);
            }
        }
    }
}

// ---------------------------------------------------------------------------
// Tensor-core flash attention (causal), balanced pairing, 4-stage KV
// pipeline with a SINGLE __syncthreads per tile (stage(t+3) != stage(t)).
// ---------------------------------------------------------------------------
#define AROWB 272
#define KROWB 144
#define QBYTES (128*AROWB)          // 34816
#define KVB (64*KROWB)              // 9216
#define ASTAGE (2*KVB)              // 18432
#define ATT_SMEM (QBYTES + 4*ASTAGE)  // 108544

__global__ __launch_bounds__(256, 2)
void attn_mma_kernel()
{
    extern __shared__ char smem[];
    const uint32_t sb = smem_u32(smem);
    const uint32_t Qs = sb;
    const uint32_t St0 = sb + QBYTES;

    const int bh = blockIdx.y;
    const int b = bh >> 4, h = bh & 15;

    const int tid = threadIdx.x;
    const int lane = tid & 31;
    const int w = tid >> 5;

    const char* Kg = (const char*)(g_Kc + (size_t)bh * SEQ * 64);
    const char* Vg = (const char*)(g_Vc + (size_t)bh * SEQ * 64);

    const uint32_t qLd = Qs + (w * 16 + (lane & 15)) * AROWB + (lane >> 4) * 16;
    const uint32_t kRow = ((lane >> 4) & 1) * 8 + (lane & 7);
    const uint32_t kCol = ((lane >> 3) & 1) * 16;
    const uint32_t vRow = ((lane >> 3) & 1) * 8 + (lane & 7);
    const uint32_t vCol = ((lane >> 4) & 1) * 16;

    const int g = lane >> 2;
    const int cq = (lane & 3) * 2;

    // per-thread KV loader coords
    const int kvIdx = tid;   // 0..255; <128 -> K rows pair, >=128 -> V
    // (loads below use the same addressing pattern as before)

#pragma unroll 1
    for (int task = 0; task < 2; task++) {
        const int qt = task ? (15 - blockIdx.x) : blockIdx.x;
        const int q0 = qt * 128;
        const char* Qg = (const char*)(g_Qc + ((size_t)bh * SEQ + q0) * 128);
        const int nt = qt * 2 + 2;

        if (task) __syncthreads();   // protect smem reuse across tasks

        // ---- prologue: group0 = Q + KV0 ; group1 = KV1 ; group2 = KV2 ----
#pragma unroll
        for (int i = 0; i < 8; i++) {
            int idx = tid + i * 256;
            int r = idx >> 4, ch = (idx & 15) * 16;
            CP_ASYNC16(Qs + r * AROWB + ch, Qg + r * 256 + ch);
        }
#pragma unroll 1
        for (int p = 0; p < 3; p++) {
            if (p < nt) {
                const uint32_t st = St0 + p * ASTAGE;
                const char* Kn = Kg + (size_t)p * 64 * 128;
                const char* Vn = Vg + (size_t)p * 64 * 128;
#pragma unroll
                for (int i = 0; i < 4; i++) {
                    int idx = tid + i * 256;
                    if (idx < 512) {
                        int r = idx >> 3, ch = (idx & 7) * 16;
                        CP_ASYNC16(st + r * KROWB + ch, Kn + r * 128 + ch);
                    } else {
                        int j = idx - 512;
                        int r = j >> 3, ch = (j & 7) * 16;
                        CP_ASYNC16(st + KVB + r * KROWB + ch, Vn + r * 128 + ch);
                    }
                }
            }
            CP_COMMIT();
        }

        float of[8][4];
#pragma unroll
        for (int i = 0; i < 8; i++)
#pragma unroll
            for (int q = 0; q < 4; q++) of[i][q] = 0.f;
        float m0r = -1e30f, m1r = -1e30f, l0r = 0.f, l1r = 0.f;
        uint32_t qh[4][4], ql[4][4];

        const int wrow = q0 + w * 16;
        const int row0 = wrow + g;
        const int row1 = row0 + 8;

        for (int t = 0; t < nt; t++) {
            CP_WAIT2();              // chunk t complete (t+1, t+2 in flight)
            __syncthreads();

            // issue prefetch for t+3 into stage (t+3)&3 (≠ stage t&3)
            if (t + 3 < nt) {
                const uint32_t stN = St0 + ((t + 3) & 3) * ASTAGE;
                const char* Kn = Kg + (size_t)(t + 3) * 64 * 128;
                const char* Vn = Vg + (size_t)(t + 3) * 64 * 128;
#pragma unroll
                for (int i = 0; i < 4; i++) {
                    int idx = tid + i * 256;
                    if (idx < 512) {
                        int r = idx >> 3, ch = (idx & 7) * 16;
                        CP_ASYNC16(stN + r * KROWB + ch, Kn + r * 128 + ch);
                    } else {
                        int j = idx - 512;
                        int r = j >> 3, ch = (j & 7) * 16;
                        CP_ASYNC16(stN + KVB + r * KROWB + ch, Vn + r * 128 + ch);
                    }
                }
            }
            CP_COMMIT();

            if (t == 0) {
#pragma unroll
                for (int ks = 0; ks < 4; ks++) {
                    LDM_X4(qh[ks][0], qh[ks][1], qh[ks][2], qh[ks][3], qLd + ks * 32);
                    LDM_X4(ql[ks][0], ql[ks][1], ql[ks][2], ql[ks][3], qLd + 128 + ks * 32);
                }
            }

            const int j0 = t * 64;
            if (j0 <= wrow + 15) {
                const uint32_t stK = St0 + (t & 3) * ASTAGE;
                const uint32_t stV = stK + KVB;
                const uint32_t kLd = stK + kRow * KROWB + kCol;
                const uint32_t vLd = stV + vRow * KROWB + vCol;

                float sc[8][4];
#pragma unroll
                for (int i = 0; i < 8; i++)
#pragma unroll
                    for (int q = 0; q < 4; q++) sc[i][q] = 0.f;

#pragma unroll
                for (int ks = 0; ks < 4; ks++) {
                    uint32_t bk[8][2];
#pragma unroll
                    for (int p = 0; p < 4; p++)
                        LDM_X4(bk[2*p][0], bk[2*p][1], bk[2*p+1][0], bk[2*p+1][1],
                               kLd + p * 16 * KROWB + ks * 32);
#pragma unroll
                    for (int nb = 0; nb < 8; nb++) {
                        MMA16816(sc[nb], qh[ks], bk[nb]);
                        MMA16816(sc[nb], ql[ks], bk[nb]);
                    }
                }

                const bool domask = (j0 + 63 > wrow);
                if (domask) {
#pragma unroll
                    for (int nb = 0; nb < 8; nb++) {
                        int col = j0 + nb * 8 + cq;
                        if (col     > row0) sc[nb][0] = -1e30f;
                        if (col + 1 > row0) sc[nb][1] = -1e30f;
                        if (col     > row1) sc[nb][2] = -1e30f;
                        if (col + 1 > row1) sc[nb][3] = -1e30f;
                    }
                }

                float mx0 = -1e30f, mx1 = -1e30f;
#pragma unroll
                for (int nb = 0; nb < 8; nb++) {
                    mx0 = fmaxf(mx0, fmaxf(sc[nb][0], sc[nb][1]));
                    mx1 = fmaxf(mx1, fmaxf(sc[nb][2], sc[nb][3]));
                }
                mx0 = fmaxf(mx0, __shfl_xor_sync(0xffffffffu, mx0, 1));
                mx0 = fmaxf(mx0, __shfl_xor_sync(0xffffffffu, mx0, 2));
                mx1 = fmaxf(mx1, __shfl_xor_sync(0xffffffffu, mx1, 1));
                mx1 = fmaxf(mx1, __shfl_xor_sync(0xffffffffu, mx1, 2));

                float mn0 = fmaxf(m0r, mx0), mn1 = fmaxf(m1r, mx1);
                float al0 = __expf(m0r - mn0), al1 = __expf(m1r - mn1);
                m0r = mn0; m1r = mn1;

                float rs0 = 0.f, rs1 = 0.f;
#pragma unroll
                for (int nb = 0; nb < 8; nb++) {
                    sc[nb][0] = __expf(sc[nb][0] - mn0);
                    sc[nb][1] = __expf(sc[nb][1] - mn0);
                    sc[nb][2] = __expf(sc[nb][2] - mn1);
                    sc[nb][3] = __expf(sc[nb][3] - mn1);
                    rs0 += sc[nb][0] + sc[nb][1];
                    rs1 += sc[nb][2] + sc[nb][3];
                }
                rs0 += __shfl_xor_sync(0xffffffffu, rs0, 1);
                rs0 += __shfl_xor_sync(0xffffffffu, rs0, 2);
                rs1 += __shfl_xor_sync(0xffffffffu, rs1, 1);
                rs1 += __shfl_xor_sync(0xffffffffu, rs1, 2);
                l0r = l0r * al0 + rs0;
                l1r = l1r * al1 + rs1;

#pragma unroll
                for (int i = 0; i < 8; i++) {
                    of[i][0] *= al0; of[i][1] *= al0;
                    of[i][2] *= al1; of[i][3] *= al1;
                }

#pragma unroll
                for (int ks = 0; ks < 4; ks++) {
                    uint32_t aPh[4];
                    float* s0 = sc[2 * ks];
                    float* s1 = sc[2 * ks + 1];
                    aPh[0] = packh(s0[0], s0[1]);
                    aPh[1] = packh(s0[2], s0[3]);
                    aPh[2] = packh(s1[0], s1[1]);
                    aPh[3] = packh(s1[2], s1[3]);
#pragma unroll
                    for (int p = 0; p < 4; p++) {
                        uint32_t vh[4];
                        LDM_X4_T(vh[0], vh[1], vh[2], vh[3],
                                 vLd + ks * 16 * KROWB + p * 32);
                        MMA16816(of[2*p],     aPh, vh);
                        MMA16816(of[2*p + 1], aPh, vh + 2);
                    }
                }
            }
        }

        float inv0 = 1.f / l0r, inv1 = 1.f / l1r;
        __half* ar0 = g_Acat + ((size_t)(b * SEQ + row0)) * 2048 + h * 64;
        __half* ar1 = g_Acat + ((size_t)(b * SEQ + row1)) * 2048 + h * 64;
#pragma unroll
        for (int nb = 0; nb < 8; nb++) {
            int d = nb * 8 + cq;
            float v0 = of[nb][0] * inv0, v1 = of[nb][1] * inv0;
            uint32_t hp = packh(v0, v1);
            __half2 hh = *(__half2*)&hp;
            uint32_t lp = packh(v0 - __low2float(hh), v1 - __high2float(hh));
            *(uint32_t*)(ar0 + d) = hp;
            *(uint32_t*)(ar0 + 1024 + d) = lp;
            float v2 = of[nb][2] * inv1, v3 = of[nb][3] * inv1;
            uint32_t hp1 = packh(v2, v3);
            __half2 hh1 = *(__half2*)&hp1;
            uint32_t lp1 = packh(v2 - __low2float(hh1), v3 - __high2float(hh1));
            *(uint32_t*)(ar1 + d) = hp1;
            *(uint32_t*)(ar1 + 1024 + d) = lp1;
        }
    }
}

// ---------------------------------------------------------------------------
// Launch
// ---------------------------------------------------------------------------
extern "C" void kernel_launch(void* const* d_in, const int* in_sizes, int n_in,
                              void* d_out, int out_size)
{
    const float* x  = (const float*)d_in[0];
    const float* Wq = (const float*)d_in[2];
    const float* Wk = (const float*)d_in[3];
    const float* Wv = (const float*)d_in[4];
    const float* Wo = (const float*)d_in[5];
    float* out = (float*)d_out;

    void *xc, *ac, *wq16, *wk16, *wv16, *wo16, *qc, *kc, *vc;
    cudaGetSymbolAddress(&xc, g_Xcat);
    cudaGetSymbolAddress(&ac, g_Acat);
    cudaGetSymbolAddress(&wq16, g_Wq16);
    cudaGetSymbolAddress(&wk16, g_Wk16);
    cudaGetSymbolAddress(&wv16, g_Wv16);
    cudaGetSymbolAddress(&wo16, g_Wo16);
    cudaGetSymbolAddress(&qc, g_Qc);
    cudaGetSymbolAddress(&kc, g_Kc);
    cudaGetSymbolAddress(&vc, g_Vc);

    rope_table_kernel<<<(SEQ * 32 + 255) / 256, 256>>>();

    split_kernel<<<(MTOT * 256 + 255) / 256, 256>>>(x, (__half*)xc, MTOT * 256);
    w16all_kernel<<<dim3(1024, 4), 256>>>(
        Wq, Wk, Wv, Wo,
        (__half*)wq16, (__half*)wk16, (__half*)wv16, (__half*)wo16);

    cudaFuncSetAttribute(hmma_gemm<1>, cudaFuncAttributeMaxDynamicSharedMemorySize, GSMEM);
    cudaFuncSetAttribute(hmma_gemm<0>, cudaFuncAttributeMaxDynamicSharedMemorySize, GSMEM);

    hmma_gemm<1><<<dim3(MTOT / 64, 24), 256, GSMEM>>>(
        (const __half*)xc, (const __half*)wq16,
        (const __half*)wk16, (const __half*)wv16,
        (float*)qc, (float*)kc, (float*)vc);

    cudaFuncSetAttribute(attn_mma_kernel,
                         cudaFuncAttributeMaxDynamicSharedMemorySize, ATT_SMEM);
    attn_mma_kernel<<<dim3(8, BH), 256, ATT_SMEM>>>();

    hmma_gemm<0><<<dim3(MTOT / 64, 8), 256, GSMEM>>>(
        (const __half*)ac, (const __half*)wo16,
        nullptr, nullptr, out, nullptr, nullptr);
}

// round 16
// speedup vs baseline: 1.0868x; 1.0868x over previous
#include <cuda_runtime.h>
#include <cuda_fp16.h>
#include <math.h>
#include <stdint.h>

#define BATCH 2
#define SEQ 2048
#define DMODEL 1024
#define NH 16
#define DH 64
#define MTOT (BATCH*SEQ)
#define BH (BATCH*NH)

// ---------------------------------------------------------------------------
// Device global scratch
// ---------------------------------------------------------------------------
__device__ float g_cos[SEQ*32];
__device__ float g_sin[SEQ*32];
__device__ __align__(128) __half g_Xcat[(size_t)MTOT*2048];
__device__ __align__(128) __half g_Acat[(size_t)MTOT*2048];
__device__ __align__(128) __half g_Wq16[1024*1024];
__device__ __align__(128) __half g_Wk16[1024*1024];
__device__ __align__(128) __half g_Wv16[1024*1024];
__device__ __align__(128) __half g_Wo16[1024*1024];
__device__ __align__(128) __half g_Qc[(size_t)BH*SEQ*64];
__device__ __align__(128) __half g_Kc[(size_t)BH*SEQ*64];
__device__ __align__(128) __half g_Vc[(size_t)BH*SEQ*64];

__device__ __forceinline__ uint32_t smem_u32(const void* p) {
    uint32_t a;
    asm("{ .reg .u64 t; cvta.to.shared.u64 t, %1; cvt.u32.u64 %0, t; }"
        : "=r"(a) : "l"(p));
    return a;
}
#define CP_ASYNC16(dst, src) \
    asm volatile("cp.async.cg.shared.global [%0], [%1], 16;" \
                 :: "r"(dst), "l"(src) : "memory")
#define CP_COMMIT() asm volatile("cp.async.commit_group;" ::: "memory")
#define CP_WAIT0()  asm volatile("cp.async.wait_group 0;" ::: "memory")
#define CP_WAIT1()  asm volatile("cp.async.wait_group 1;" ::: "memory")
#define LDM_X4(r0, r1, r2, r3, addr) \
    asm volatile("ldmatrix.sync.aligned.m8n8.x4.shared.b16 {%0,%1,%2,%3}, [%4];" \
                 : "=r"(r0), "=r"(r1), "=r"(r2), "=r"(r3) : "r"(addr))
#define LDM_X4_T(r0, r1, r2, r3, addr) \
    asm volatile("ldmatrix.sync.aligned.m8n8.x4.trans.shared.b16 {%0,%1,%2,%3}, [%4];" \
                 : "=r"(r0), "=r"(r1), "=r"(r2), "=r"(r3) : "r"(addr))
#define MMA16816(c, a, b) \
    asm volatile("mma.sync.aligned.m16n8k16.row.col.f32.f16.f16.f32 " \
                 "{%0,%1,%2,%3}, {%4,%5,%6,%7}, {%8,%9}, {%0,%1,%2,%3};" \
                 : "+f"((c)[0]), "+f"((c)[1]), "+f"((c)[2]), "+f"((c)[3]) \
                 : "r"((a)[0]), "r"((a)[1]), "r"((a)[2]), "r"((a)[3]), \
                   "r"((b)[0]), "r"((b)[1]))

__device__ __forceinline__ uint32_t packh(float a, float b) {
    uint32_t r;
    asm("cvt.rn.f16x2.f32 %0, %2, %1;" : "=r"(r) : "f"(a), "f"(b));
    return r;
}

// ---------------------------------------------------------------------------
// RoPE table
// ---------------------------------------------------------------------------
__global__ void rope_table_kernel()
{
    int idx = blockIdx.x * blockDim.x + threadIdx.x;
    if (idx >= SEQ * 32) return;
    int p = idx & 31;
    int s = idx >> 5;
    double inv = pow(10000.0, -(double)p / 32.0);
    double sd, cd;
    sincos((double)s * inv, &sd, &cd);
    g_cos[idx] = (float)cd;
    g_sin[idx] = (float)sd;
}

// ---------------------------------------------------------------------------
// fp32 -> fp16 hi/lo split (x)
// ---------------------------------------------------------------------------
__global__ void split_kernel(const float* __restrict__ src,
                             __half* __restrict__ dst, int n4)
{
    int i = blockIdx.x * blockDim.x + threadIdx.x;
    if (i >= n4) return;
    int row = i >> 8;
    int kq = (i & 255) << 2;
    float4 v = *(const float4*)&src[(size_t)row * 1024 + kq];
    float vv[4] = {v.x, v.y, v.z, v.w};
    ushort4 hp, lp;
    unsigned short* h = (unsigned short*)&hp;
    unsigned short* l = (unsigned short*)&lp;
#pragma unroll
    for (int q = 0; q < 4; q++) {
        __half hh = __float2half_rn(vv[q]);
        h[q] = *(unsigned short*)&hh;
        __half ll = __float2half_rn(vv[q] - __half2float(hh));
        l[q] = *(unsigned short*)&ll;
    }
    size_t rb = (size_t)row * 2048;
    *(ushort4*)&dst[rb + kq] = hp;
    *(ushort4*)&dst[rb + 1024 + kq] = lp;
}

// ---------------------------------------------------------------------------
// fp32 -> fp16 convert, all 4 weights in one launch
// ---------------------------------------------------------------------------
__global__ void w16all_kernel(const float* __restrict__ s0, const float* __restrict__ s1,
                              const float* __restrict__ s2, const float* __restrict__ s3,
                              __half* __restrict__ d0, __half* __restrict__ d1,
                              __half* __restrict__ d2, __half* __restrict__ d3)
{
    int i = blockIdx.x * blockDim.x + threadIdx.x;
    if (i >= 1024 * 256) return;
    const float* s; __half* d;
    switch (blockIdx.y) {
        case 0: s = s0; d = d0; break;
        case 1: s = s1; d = d1; break;
        case 2: s = s2; d = d2; break;
        default: s = s3; d = d3; break;
    }
    float4 v = *(const float4*)&s[(size_t)i * 4];
    ushort4 hp;
    unsigned short* h = (unsigned short*)&hp;
    __half h0 = __float2half_rn(v.x); h[0] = *(unsigned short*)&h0;
    __half h1 = __float2half_rn(v.y); h[1] = *(unsigned short*)&h1;
    __half h2 = __float2half_rn(v.z); h[2] = *(unsigned short*)&h2;
    __half h3 = __float2half_rn(v.w); h[3] = *(unsigned short*)&h3;
    *(ushort4*)&d[(size_t)i * 4] = hp;
}

// ---------------------------------------------------------------------------
// HMMA fp16 2-term GEMM, fused hi+lo per W-chunk (R14).
// Q/K epilogues both write single fp16 [row][64] with RoPE; Q pre-scaled 1/8.
// ---------------------------------------------------------------------------
#define ALO_OFF 8192
#define W_OFF 16384
#define STG4 32768
#define GSMEM (2*STG4)
#define NCH4 16

template<int QKV>
__global__ __launch_bounds__(256, 3)
void hmma_gemm(const __half* __restrict__ A,
               const __half* __restrict__ W0,
               const __half* __restrict__ W1,
               const __half* __restrict__ W2,
               float* __restrict__ Y0, float* __restrict__ Y1,
               float* __restrict__ Y2)
{
    extern __shared__ char smem[];
    const uint32_t sb = smem_u32(smem);
    const int tid = threadIdx.x;
    const int lane = tid & 31;
    const int w = tid >> 5;
    const int wm = w & 1, wn = w >> 1;

    const int m0 = blockIdx.x * 64;
    const int by = blockIdx.y;
    const int ws = QKV ? (by >> 3) : 0;
    const int nblk = by & 7;

    const __half* W = W0;
    float* Y = Y0;
    if (QKV) {
        if (ws == 1) { W = W1; Y = Y1; }
        else if (ws == 2) { W = W2; Y = Y2; }
    }

    uint32_t dA[2]; const __half* sA[2];
#pragma unroll
    for (int i = 0; i < 2; i++) {
        int u = tid + i * 256;
        int r = u >> 3, c16 = u & 7;
        dA[i] = sb + r * 128 + ((c16 ^ (r & 7)) * 16);
        sA[i] = A + (size_t)(m0 + r) * 2048 + c16 * 8;
    }
    uint32_t dW[4]; const __half* sW[4];
#pragma unroll
    for (int i = 0; i < 4; i++) {
        int u = tid + i * 256;
        int r = u >> 3, c16 = u & 7;
        dW[i] = sb + W_OFF + r * 128 + ((c16 ^ (r & 7)) * 16);
        sW[i] = W + (size_t)(nblk * 128 + r) * 1024 + c16 * 8;
    }

    float c[2][4][4];
#pragma unroll
    for (int i = 0; i < 2; i++)
#pragma unroll
        for (int j = 0; j < 4; j++)
#pragma unroll
            for (int q = 0; q < 4; q++) c[i][j][q] = 0.f;

    {
#pragma unroll
        for (int i = 0; i < 2; i++) {
            CP_ASYNC16(dA[i], sA[i]);
            CP_ASYNC16(dA[i] + ALO_OFF, sA[i] + 1024);
        }
#pragma unroll
        for (int i = 0; i < 4; i++) CP_ASYNC16(dW[i], sW[i]);
        CP_COMMIT();
    }

    const int arow = wm * 32 + (lane & 15);
    const uint32_t axor = (uint32_t)(arow & 7) << 4;
    const uint32_t aBase = sb + arow * 128;
    const uint32_t acol0 = ((uint32_t)(lane >> 4)) * 16;
    const int brow = wn * 32 + ((lane >> 4) & 1) * 8 + (lane & 7);
    const uint32_t bxor = (uint32_t)(brow & 7) << 4;
    const uint32_t bBase = sb + W_OFF + brow * 128;
    const uint32_t bcol0 = ((uint32_t)((lane >> 3) & 1)) * 16;

    for (int cc = 0; cc < NCH4; cc++) {
        CP_WAIT0();
        __syncthreads();
        if (cc + 1 < NCH4) {
            uint32_t so = ((cc + 1) & 1) * STG4;
            int k = (cc + 1) * 64;
#pragma unroll
            for (int i = 0; i < 2; i++) {
                CP_ASYNC16(dA[i] + so, sA[i] + k);
                CP_ASYNC16(dA[i] + ALO_OFF + so, sA[i] + k + 1024);
            }
#pragma unroll
            for (int i = 0; i < 4; i++) CP_ASYNC16(dW[i] + so, sW[i] + k);
            CP_COMMIT();
        }

        const uint32_t so = (cc & 1) * STG4;
#pragma unroll
        for (int kh = 0; kh < 4; kh++) {
            uint32_t ah[2][4], al[2][4], b[4][2];
#pragma unroll
            for (int mt = 0; mt < 2; mt++) {
                uint32_t off = mt * 2048 + ((kh * 32 + acol0) ^ axor);
                LDM_X4(ah[mt][0], ah[mt][1], ah[mt][2], ah[mt][3],
                       aBase + so + off);
                LDM_X4(al[mt][0], al[mt][1], al[mt][2], al[mt][3],
                       aBase + ALO_OFF + so + off);
            }
#pragma unroll
            for (int p = 0; p < 2; p++)
                LDM_X4(b[2*p][0], b[2*p][1], b[2*p+1][0], b[2*p+1][1],
                       bBase + so + p * 2048 + ((kh * 32 + bcol0) ^ bxor));
#pragma unroll
            for (int mt = 0; mt < 2; mt++)
#pragma unroll
                for (int nt = 0; nt < 4; nt++) {
                    MMA16816(c[mt][nt], ah[mt], b[nt]);
                    MMA16816(c[mt][nt], al[mt], b[nt]);
                }
        }
    }

    if (QKV && ws == 2) {
        // V: single fp16 -> g_Vc [row][64]
#pragma unroll
        for (int mt = 0; mt < 2; mt++) {
            int mrow = m0 + wm * 32 + mt * 16 + (lane >> 2);
#pragma unroll
            for (int nt = 0; nt < 4; nt++) {
                int n = nblk * 128 + wn * 32 + nt * 8 + (lane & 3) * 2;
                int h = n >> 6, d0 = n & 63;
                int b = mrow >> 11, s = mrow & (SEQ - 1);
                __half* dst = (__half*)Y +
                    (((size_t)((b << 4) + h) * SEQ + s) * 64 + d0);
                *(uint32_t*)dst = packh(c[mt][nt][0], c[mt][nt][1]);
                *(uint32_t*)(dst + 8 * 64) = packh(c[mt][nt][2], c[mt][nt][3]);
            }
        }
    } else if (QKV) {
        // Q/K: smem exchange + RoPE, single fp16 out (Q pre-scaled by 1/8)
        __syncthreads();
        float* ot = (float*)smem;
        {
#pragma unroll
            for (int mt = 0; mt < 2; mt++) {
                int ml = wm * 32 + mt * 16 + (lane >> 2);
#pragma unroll
                for (int nt = 0; nt < 4; nt++) {
                    int n = wn * 32 + nt * 8 + (lane & 3) * 2;
                    ot[ml * 132 + n]     = c[mt][nt][0];
                    ot[ml * 132 + n + 1] = c[mt][nt][1];
                    ot[(ml + 8) * 132 + n]     = c[mt][nt][2];
                    ot[(ml + 8) * 132 + n + 1] = c[mt][nt][3];
                }
            }
        }
        __syncthreads();
        {
            const int dq = (tid & 7) * 4;
            const float qs = (ws == 0) ? 0.125f : 1.f;
#pragma unroll
            for (int rp = 0; rp < 2; rp++) {
                int ml = (tid >> 3) + rp * 32;
                int mrow = m0 + ml;
                int b = mrow >> 11, s = mrow & (SEQ - 1);
                float4 cs4 = *(const float4*)&g_cos[s * 32 + dq];
                float4 sn4 = *(const float4*)&g_sin[s * 32 + dq];
                float csv[4] = {cs4.x, cs4.y, cs4.z, cs4.w};
                float snv[4] = {sn4.x, sn4.y, sn4.z, sn4.w};
#pragma unroll
                for (int hh2 = 0; hh2 < 2; hh2++) {
                    int h = nblk * 2 + hh2;
                    float r1[4], r2[4];
#pragma unroll
                    for (int i = 0; i < 4; i++) {
                        float v1 = ot[ml * 132 + hh2 * 64 + dq + i];
                        float v2 = ot[ml * 132 + hh2 * 64 + dq + 32 + i];
                        r1[i] = (v1 * csv[i] - v2 * snv[i]) * qs;
                        r2[i] = (v2 * csv[i] + v1 * snv[i]) * qs;
                    }
                    __half* kd = (__half*)Y + ((size_t)((b << 4) + h) * SEQ + s) * 64;
                    *(uint2*)(kd + dq)      = make_uint2(packh(r1[0], r1[1]), packh(r1[2], r1[3]));
                    *(uint2*)(kd + dq + 32) = make_uint2(packh(r2[0], r2[1]), packh(r2[2], r2[3]));
                }
            }
        }
    } else {
#pragma unroll
        for (int mt = 0; mt < 2; mt++) {
            int mrow = m0 + wm * 32 + mt * 16 + (lane >> 2);
#pragma unroll
            for (int nt = 0; nt < 4; nt++) {
                int n = nblk * 128 + wn * 32 + nt * 8 + (lane & 3) * 2;
                float* dst = Y + (size_t)mrow * 1024 + n;
                *(float2*)dst = make_float2(c[mt][nt][0], c[mt][nt][1]);
                *(float2*)(dst + 8 * 1024) = make_float2(c[mt][nt][2], c[mt][nt][3]);
            }
        }
    }
}

// ---------------------------------------------------------------------------
// Tensor-core flash attention (causal), balanced pairing, 2-stage KV (R14),
// Q single fp16 [row][64] (residual dropped), scale pre-folded.
// ---------------------------------------------------------------------------
#define KROWB 144
#define QBYTES (128*KROWB)          // 18432
#define KVB (64*KROWB)              // 9216
#define ASTAGE (2*KVB)              // 18432
#define ATT_SMEM (QBYTES + 2*ASTAGE)  // 55296

__global__ __launch_bounds__(256, 2)
void attn_mma_kernel()
{
    extern __shared__ char smem[];
    const uint32_t sb = smem_u32(smem);
    const uint32_t Qs = sb;
    const uint32_t St0 = sb + QBYTES;

    const int bh = blockIdx.y;
    const int b = bh >> 4, h = bh & 15;

    const int tid = threadIdx.x;
    const int lane = tid & 31;
    const int w = tid >> 5;

    const char* Kg = (const char*)(g_Kc + (size_t)bh * SEQ * 64);
    const char* Vg = (const char*)(g_Vc + (size_t)bh * SEQ * 64);

    const uint32_t qLd = Qs + (w * 16 + (lane & 15)) * KROWB + (lane >> 4) * 16;
    const uint32_t kRow = ((lane >> 4) & 1) * 8 + (lane & 7);
    const uint32_t kCol = ((lane >> 3) & 1) * 16;
    const uint32_t vRow = ((lane >> 3) & 1) * 8 + (lane & 7);
    const uint32_t vCol = ((lane >> 4) & 1) * 16;

    const int g = lane >> 2;
    const int cq = (lane & 3) * 2;

#pragma unroll 1
    for (int task = 0; task < 2; task++) {
        const int qt = task ? (15 - blockIdx.x) : blockIdx.x;
        const int q0 = qt * 128;
        const char* Qg = (const char*)(g_Qc + ((size_t)bh * SEQ + q0) * 64);

        if (task) __syncthreads();

        // prologue: Q (128 rows x 128B) + KV tile 0 (one group)
#pragma unroll
        for (int i = 0; i < 4; i++) {
            int idx = tid + i * 256;
            int r = idx >> 3, ch = (idx & 7) * 16;
            CP_ASYNC16(Qs + r * KROWB + ch, Qg + r * 128 + ch);
        }
#pragma unroll
        for (int i = 0; i < 4; i++) {
            int idx = tid + i * 256;
            if (idx < 512) {
                int r = idx >> 3, ch = (idx & 7) * 16;
                CP_ASYNC16(St0 + r * KROWB + ch, Kg + r * 128 + ch);
            } else {
                int j = idx - 512;
                int r = j >> 3, ch = (j & 7) * 16;
                CP_ASYNC16(St0 + KVB + r * KROWB + ch, Vg + r * 128 + ch);
            }
        }
        CP_COMMIT();

        float of[8][4];
#pragma unroll
        for (int i = 0; i < 8; i++)
#pragma unroll
            for (int q = 0; q < 4; q++) of[i][q] = 0.f;
        float m0r = -1e30f, m1r = -1e30f, l0r = 0.f, l1r = 0.f;
        uint32_t qh[4][4];

        const int wrow = q0 + w * 16;
        const int row0 = wrow + g;
        const int row1 = row0 + 8;

        const int nt = qt * 2 + 2;
        for (int t = 0; t < nt; t++) {
            if (t + 1 < nt) {
                const uint32_t stN = St0 + ((t + 1) & 1) * ASTAGE;
                const char* Kn = Kg + (size_t)(t + 1) * 64 * 128;
                const char* Vn = Vg + (size_t)(t + 1) * 64 * 128;
#pragma unroll
                for (int i = 0; i < 4; i++) {
                    int idx = tid + i * 256;
                    if (idx < 512) {
                        int r = idx >> 3, ch = (idx & 7) * 16;
                        CP_ASYNC16(stN + r * KROWB + ch, Kn + r * 128 + ch);
                    } else {
                        int j = idx - 512;
                        int r = j >> 3, ch = (j & 7) * 16;
                        CP_ASYNC16(stN + KVB + r * KROWB + ch, Vn + r * 128 + ch);
                    }
                }
            }
            CP_COMMIT();
            CP_WAIT1();
            __syncthreads();

            if (t == 0) {
#pragma unroll
                for (int ks = 0; ks < 4; ks++)
                    LDM_X4(qh[ks][0], qh[ks][1], qh[ks][2], qh[ks][3], qLd + ks * 32);
            }

            const int j0 = t * 64;
            if (j0 <= wrow + 15) {
                const uint32_t stK = St0 + (t & 1) * ASTAGE;
                const uint32_t stV = stK + KVB;
                const uint32_t kLd = stK + kRow * KROWB + kCol;
                const uint32_t vLd = stV + vRow * KROWB + vCol;

                float sc[8][4];
#pragma unroll
                for (int i = 0; i < 8; i++)
#pragma unroll
                    for (int q = 0; q < 4; q++) sc[i][q] = 0.f;

#pragma unroll
                for (int ks = 0; ks < 4; ks++) {
                    uint32_t bk[8][2];
#pragma unroll
                    for (int p = 0; p < 4; p++)
                        LDM_X4(bk[2*p][0], bk[2*p][1], bk[2*p+1][0], bk[2*p+1][1],
                               kLd + p * 16 * KROWB + ks * 32);
#pragma unroll
                    for (int nb = 0; nb < 8; nb++)
                        MMA16816(sc[nb], qh[ks], bk[nb]);
                }

                const bool domask = (j0 + 63 > wrow);
                if (domask) {
#pragma unroll
                    for (int nb = 0; nb < 8; nb++) {
                        int col = j0 + nb * 8 + cq;
                        if (col     > row0) sc[nb][0] = -1e30f;
                        if (col + 1 > row0) sc[nb][1] = -1e30f;
                        if (col     > row1) sc[nb][2] = -1e30f;
                        if (col + 1 > row1) sc[nb][3] = -1e30f;
                    }
                }

                float mx0 = -1e30f, mx1 = -1e30f;
#pragma unroll
                for (int nb = 0; nb < 8; nb++) {
                    mx0 = fmaxf(mx0, fmaxf(sc[nb][0], sc[nb][1]));
                    mx1 = fmaxf(mx1, fmaxf(sc[nb][2], sc[nb][3]));
                }
                mx0 = fmaxf(mx0, __shfl_xor_sync(0xffffffffu, mx0, 1));
                mx0 = fmaxf(mx0, __shfl_xor_sync(0xffffffffu, mx0, 2));
                mx1 = fmaxf(mx1, __shfl_xor_sync(0xffffffffu, mx1, 1));
                mx1 = fmaxf(mx1, __shfl_xor_sync(0xffffffffu, mx1, 2));

                float mn0 = fmaxf(m0r, mx0), mn1 = fmaxf(m1r, mx1);
                float al0 = __expf(m0r - mn0), al1 = __expf(m1r - mn1);
                m0r = mn0; m1r = mn1;

                float rs0 = 0.f, rs1 = 0.f;
#pragma unroll
                for (int nb = 0; nb < 8; nb++) {
                    sc[nb][0] = __expf(sc[nb][0] - mn0);
                    sc[nb][1] = __expf(sc[nb][1] - mn0);
                    sc[nb][2] = __expf(sc[nb][2] - mn1);
                    sc[nb][3] = __expf(sc[nb][3] - mn1);
                    rs0 += sc[nb][0] + sc[nb][1];
                    rs1 += sc[nb][2] + sc[nb][3];
                }
                rs0 += __shfl_xor_sync(0xffffffffu, rs0, 1);
                rs0 += __shfl_xor_sync(0xffffffffu, rs0, 2);
                rs1 += __shfl_xor_sync(0xffffffffu, rs1, 1);
                rs1 += __shfl_xor_sync(0xffffffffu, rs1, 2);
                l0r = l0r * al0 + rs0;
                l1r = l1r * al1 + rs1;

#pragma unroll
                for (int i = 0; i < 8; i++) {
                    of[i][0] *= al0; of[i][1] *= al0;
                    of[i][2] *= al1; of[i][3] *= al1;
                }

#pragma unroll
                for (int ks = 0; ks < 4; ks++) {
                    uint32_t aPh[4];
                    float* s0 = sc[2 * ks];
                    float* s1 = sc[2 * ks + 1];
                    aPh[0] = packh(s0[0], s0[1]);
                    aPh[1] = packh(s0[2], s0[3]);
                    aPh[2] = packh(s1[0], s1[1]);
                    aPh[3] = packh(s1[2], s1[3]);
#pragma unroll
                    for (int p = 0; p < 4; p++) {
                        uint32_t vh[4];
                        LDM_X4_T(vh[0], vh[1], vh[2], vh[3],
                                 vLd + ks * 16 * KROWB + p * 32);
                        MMA16816(of[2*p],     aPh, vh);
                        MMA16816(of[2*p + 1], aPh, vh + 2);
                    }
                }
            }
            __syncthreads();
        }

        float inv0 = 1.f / l0r, inv1 = 1.f / l1r;
        __half* ar0 = g_Acat + ((size_t)(b * SEQ + row0)) * 2048 + h * 64;
        __half* ar1 = g_Acat + ((size_t)(b * SEQ + row1)) * 2048 + h * 64;
#pragma unroll
        for (int nb = 0; nb < 8; nb++) {
            int d = nb * 8 + cq;
            float v0 = of[nb][0] * inv0, v1 = of[nb][1] * inv0;
            uint32_t hp = packh(v0, v1);
            __half2 hh = *(__half2*)&hp;
            uint32_t lp = packh(v0 - __low2float(hh), v1 - __high2float(hh));
            *(uint32_t*)(ar0 + d) = hp;
            *(uint32_t*)(ar0 + 1024 + d) = lp;
            float v2 = of[nb][2] * inv1, v3 = of[nb][3] * inv1;
            uint32_t hp1 = packh(v2, v3);
            __half2 hh1 = *(__half2*)&hp1;
            uint32_t lp1 = packh(v2 - __low2float(hh1), v3 - __high2float(hh1));
            *(uint32_t*)(ar1 + d) = hp1;
            *(uint32_t*)(ar1 + 1024 + d) = lp1;
        }
    }
}

// ---------------------------------------------------------------------------
// Launch
// ---------------------------------------------------------------------------
extern "C" void kernel_launch(void* const* d_in, const int* in_sizes, int n_in,
                              void* d_out, int out_size)
{
    const float* x  = (const float*)d_in[0];
    const float* Wq = (const float*)d_in[2];
    const float* Wk = (const float*)d_in[3];
    const float* Wv = (const float*)d_in[4];
    const float* Wo = (const float*)d_in[5];
    float* out = (float*)d_out;

    void *xc, *ac, *wq16, *wk16, *wv16, *wo16, *qc, *kc, *vc;
    cudaGetSymbolAddress(&xc, g_Xcat);
    cudaGetSymbolAddress(&ac, g_Acat);
    cudaGetSymbolAddress(&wq16, g_Wq16);
    cudaGetSymbolAddress(&wk16, g_Wk16);
    cudaGetSymbolAddress(&wv16, g_Wv16);
    cudaGetSymbolAddress(&wo16, g_Wo16);
    cudaGetSymbolAddress(&qc, g_Qc);
    cudaGetSymbolAddress(&kc, g_Kc);
    cudaGetSymbolAddress(&vc, g_Vc);

    rope_table_kernel<<<(SEQ * 32 + 255) / 256, 256>>>();

    split_kernel<<<(MTOT * 256 + 255) / 256, 256>>>(x, (__half*)xc, MTOT * 256);
    w16all_kernel<<<dim3(1024, 4), 256>>>(
        Wq, Wk, Wv, Wo,
        (__half*)wq16, (__half*)wk16, (__half*)wv16, (__half*)wo16);

    cudaFuncSetAttribute(hmma_gemm<1>, cudaFuncAttributeMaxDynamicSharedMemorySize, GSMEM);
    cudaFuncSetAttribute(hmma_gemm<0>, cudaFuncAttributeMaxDynamicSharedMemorySize, GSMEM);

    hmma_gemm<1><<<dim3(MTOT / 64, 24), 256, GSMEM>>>(
        (const __half*)xc, (const __half*)wq16,
        (const __half*)wk16, (const __half*)wv16,
        (float*)qc, (float*)kc, (float*)vc);

    cudaFuncSetAttribute(attn_mma_kernel,
                         cudaFuncAttributeMaxDynamicSharedMemorySize, ATT_SMEM);
    attn_mma_kernel<<<dim3(8, BH), 256, ATT_SMEM>>>();

    hmma_gemm<0><<<dim3(MTOT / 64, 8), 256, GSMEM>>>(
        (const __half*)ac, (const __half*)wo16,
        nullptr, nullptr, out, nullptr, nullptr);
}

// round 17
// speedup vs baseline: 1.4483x; 1.3325x over previous
#include <cuda_runtime.h>
#include <cuda_fp16.h>
#include <math.h>
#include <stdint.h>

#define BATCH 2
#define SEQ 2048
#define DMODEL 1024
#define NH 16
#define DH 64
#define MTOT (BATCH*SEQ)
#define BH (BATCH*NH)

// ---------------------------------------------------------------------------
// Device global scratch
// ---------------------------------------------------------------------------
__device__ float g_cos[SEQ*32];
__device__ float g_sin[SEQ*32];
__device__ __align__(128) __half g_X16[(size_t)MTOT*1024];
__device__ __align__(128) __half g_A16[(size_t)MTOT*1024];
__device__ __align__(128) __half g_Wq16[1024*1024];
__device__ __align__(128) __half g_Wk16[1024*1024];
__device__ __align__(128) __half g_Wv16[1024*1024];
__device__ __align__(128) __half g_Wo16[1024*1024];
__device__ __align__(128) __half g_Qc[(size_t)BH*SEQ*64];
__device__ __align__(128) __half g_Kc[(size_t)BH*SEQ*64];
__device__ __align__(128) __half g_Vc[(size_t)BH*SEQ*64];

__device__ __forceinline__ uint32_t smem_u32(const void* p) {
    uint32_t a;
    asm("{ .reg .u64 t; cvta.to.shared.u64 t, %1; cvt.u32.u64 %0, t; }"
        : "=r"(a) : "l"(p));
    return a;
}
#define CP_ASYNC16(dst, src) \
    asm volatile("cp.async.cg.shared.global [%0], [%1], 16;" \
                 :: "r"(dst), "l"(src) : "memory")
#define CP_COMMIT() asm volatile("cp.async.commit_group;" ::: "memory")
#define CP_WAIT0()  asm volatile("cp.async.wait_group 0;" ::: "memory")
#define CP_WAIT1()  asm volatile("cp.async.wait_group 1;" ::: "memory")
#define LDM_X4(r0, r1, r2, r3, addr) \
    asm volatile("ldmatrix.sync.aligned.m8n8.x4.shared.b16 {%0,%1,%2,%3}, [%4];" \
                 : "=r"(r0), "=r"(r1), "=r"(r2), "=r"(r3) : "r"(addr))
#define LDM_X4_T(r0, r1, r2, r3, addr) \
    asm volatile("ldmatrix.sync.aligned.m8n8.x4.trans.shared.b16 {%0,%1,%2,%3}, [%4];" \
                 : "=r"(r0), "=r"(r1), "=r"(r2), "=r"(r3) : "r"(addr))
#define MMA16816(c, a, b) \
    asm volatile("mma.sync.aligned.m16n8k16.row.col.f32.f16.f16.f32 " \
                 "{%0,%1,%2,%3}, {%4,%5,%6,%7}, {%8,%9}, {%0,%1,%2,%3};" \
                 : "+f"((c)[0]), "+f"((c)[1]), "+f"((c)[2]), "+f"((c)[3]) \
                 : "r"((a)[0]), "r"((a)[1]), "r"((a)[2]), "r"((a)[3]), \
                   "r"((b)[0]), "r"((b)[1]))

__device__ __forceinline__ uint32_t packh(float a, float b) {
    uint32_t r;
    asm("cvt.rn.f16x2.f32 %0, %2, %1;" : "=r"(r) : "f"(a), "f"(b));
    return r;
}

// ---------------------------------------------------------------------------
// RoPE table
// ---------------------------------------------------------------------------
__global__ void rope_table_kernel()
{
    int idx = blockIdx.x * blockDim.x + threadIdx.x;
    if (idx >= SEQ * 32) return;
    int p = idx & 31;
    int s = idx >> 5;
    double inv = pow(10000.0, -(double)p / 32.0);
    double sd, cd;
    sincos((double)s * inv, &sd, &cd);
    g_cos[idx] = (float)cd;
    g_sin[idx] = (float)sd;
}

// ---------------------------------------------------------------------------
// fp32 -> fp16 convert (generic)
// ---------------------------------------------------------------------------
__global__ void cvt16_kernel(const float* __restrict__ src,
                             __half* __restrict__ dst, int n4)
{
    int i = blockIdx.x * blockDim.x + threadIdx.x;
    if (i >= n4) return;
    float4 v = *(const float4*)&src[(size_t)i * 4];
    ushort4 hp;
    unsigned short* h = (unsigned short*)&hp;
    __half h0 = __float2half_rn(v.x); h[0] = *(unsigned short*)&h0;
    __half h1 = __float2half_rn(v.y); h[1] = *(unsigned short*)&h1;
    __half h2 = __float2half_rn(v.z); h[2] = *(unsigned short*)&h2;
    __half h3 = __float2half_rn(v.w); h[3] = *(unsigned short*)&h3;
    *(ushort4*)&dst[(size_t)i * 4] = hp;
}

// ---------------------------------------------------------------------------
// fp32 -> fp16 convert, all 4 weights in one launch
// ---------------------------------------------------------------------------
__global__ void w16all_kernel(const float* __restrict__ s0, const float* __restrict__ s1,
                              const float* __restrict__ s2, const float* __restrict__ s3,
                              __half* __restrict__ d0, __half* __restrict__ d1,
                              __half* __restrict__ d2, __half* __restrict__ d3)
{
    int i = blockIdx.x * blockDim.x + threadIdx.x;
    if (i >= 1024 * 256) return;
    const float* s; __half* d;
    switch (blockIdx.y) {
        case 0: s = s0; d = d0; break;
        case 1: s = s1; d = d1; break;
        case 2: s = s2; d = d2; break;
        default: s = s3; d = d3; break;
    }
    float4 v = *(const float4*)&s[(size_t)i * 4];
    ushort4 hp;
    unsigned short* h = (unsigned short*)&hp;
    __half h0 = __float2half_rn(v.x); h[0] = *(unsigned short*)&h0;
    __half h1 = __float2half_rn(v.y); h[1] = *(unsigned short*)&h1;
    __half h2 = __float2half_rn(v.z); h[2] = *(unsigned short*)&h2;
    __half h3 = __float2half_rn(v.w); h[3] = *(unsigned short*)&h3;
    *(ushort4*)&d[(size_t)i * 4] = hp;
}

// ---------------------------------------------------------------------------
// HMMA single-term fp16 GEMM: Y = A16 @ W16^T (fp32 accum).
// CTA tile 64x128, warp tile 32x32, occ 3. Stage = A(8KB)|W(16KB) = 24KB, x2.
// QKV=1: Q/K epilogue RoPE->fp16 (Q pre-scaled 1/8), V fp16. QKV=0: fp32 out.
// ---------------------------------------------------------------------------
#define W_OFF 8192
#define STG4 24576
#define GSMEM (2*STG4)             // 49152
#define NCH4 16

template<int QKV>
__global__ __launch_bounds__(256, 3)
void hmma_gemm(const __half* __restrict__ A,
               const __half* __restrict__ W0,
               const __half* __restrict__ W1,
               const __half* __restrict__ W2,
               float* __restrict__ Y0, float* __restrict__ Y1,
               float* __restrict__ Y2)
{
    extern __shared__ char smem[];
    const uint32_t sb = smem_u32(smem);
    const int tid = threadIdx.x;
    const int lane = tid & 31;
    const int w = tid >> 5;
    const int wm = w & 1, wn = w >> 1;

    const int m0 = blockIdx.x * 64;
    const int by = blockIdx.y;
    const int ws = QKV ? (by >> 3) : 0;
    const int nblk = by & 7;

    const __half* W = W0;
    float* Y = Y0;
    if (QKV) {
        if (ws == 1) { W = W1; Y = Y1; }
        else if (ws == 2) { W = W2; Y = Y2; }
    }

    uint32_t dA[2]; const __half* sA[2];
#pragma unroll
    for (int i = 0; i < 2; i++) {
        int u = tid + i * 256;
        int r = u >> 3, c16 = u & 7;
        dA[i] = sb + r * 128 + ((c16 ^ (r & 7)) * 16);
        sA[i] = A + (size_t)(m0 + r) * 1024 + c16 * 8;
    }
    uint32_t dW[4]; const __half* sW[4];
#pragma unroll
    for (int i = 0; i < 4; i++) {
        int u = tid + i * 256;
        int r = u >> 3, c16 = u & 7;
        dW[i] = sb + W_OFF + r * 128 + ((c16 ^ (r & 7)) * 16);
        sW[i] = W + (size_t)(nblk * 128 + r) * 1024 + c16 * 8;
    }

    float c[2][4][4];
#pragma unroll
    for (int i = 0; i < 2; i++)
#pragma unroll
        for (int j = 0; j < 4; j++)
#pragma unroll
            for (int q = 0; q < 4; q++) c[i][j][q] = 0.f;

    {
#pragma unroll
        for (int i = 0; i < 2; i++) CP_ASYNC16(dA[i], sA[i]);
#pragma unroll
        for (int i = 0; i < 4; i++) CP_ASYNC16(dW[i], sW[i]);
        CP_COMMIT();
    }

    const int arow = wm * 32 + (lane & 15);
    const uint32_t axor = (uint32_t)(arow & 7) << 4;
    const uint32_t aBase = sb + arow * 128;
    const uint32_t acol0 = ((uint32_t)(lane >> 4)) * 16;
    const int brow = wn * 32 + ((lane >> 4) & 1) * 8 + (lane & 7);
    const uint32_t bxor = (uint32_t)(brow & 7) << 4;
    const uint32_t bBase = sb + W_OFF + brow * 128;
    const uint32_t bcol0 = ((uint32_t)((lane >> 3) & 1)) * 16;

    for (int cc = 0; cc < NCH4; cc++) {
        CP_WAIT0();
        __syncthreads();
        if (cc + 1 < NCH4) {
            uint32_t so = ((cc + 1) & 1) * STG4;
            int k = (cc + 1) * 64;
#pragma unroll
            for (int i = 0; i < 2; i++) CP_ASYNC16(dA[i] + so, sA[i] + k);
#pragma unroll
            for (int i = 0; i < 4; i++) CP_ASYNC16(dW[i] + so, sW[i] + k);
            CP_COMMIT();
        }

        const uint32_t so = (cc & 1) * STG4;
#pragma unroll
        for (int kh = 0; kh < 4; kh++) {
            uint32_t a[2][4], b[4][2];
#pragma unroll
            for (int mt = 0; mt < 2; mt++)
                LDM_X4(a[mt][0], a[mt][1], a[mt][2], a[mt][3],
                       aBase + so + mt * 2048 + ((kh * 32 + acol0) ^ axor));
#pragma unroll
            for (int p = 0; p < 2; p++)
                LDM_X4(b[2*p][0], b[2*p][1], b[2*p+1][0], b[2*p+1][1],
                       bBase + so + p * 2048 + ((kh * 32 + bcol0) ^ bxor));
#pragma unroll
            for (int mt = 0; mt < 2; mt++)
#pragma unroll
                for (int nt = 0; nt < 4; nt++)
                    MMA16816(c[mt][nt], a[mt], b[nt]);
        }
    }

    if (QKV && ws == 2) {
        // V: single fp16 -> g_Vc [row][64]
#pragma unroll
        for (int mt = 0; mt < 2; mt++) {
            int mrow = m0 + wm * 32 + mt * 16 + (lane >> 2);
#pragma unroll
            for (int nt = 0; nt < 4; nt++) {
                int n = nblk * 128 + wn * 32 + nt * 8 + (lane & 3) * 2;
                int h = n >> 6, d0 = n & 63;
                int b = mrow >> 11, s = mrow & (SEQ - 1);
                __half* dst = (__half*)Y +
                    (((size_t)((b << 4) + h) * SEQ + s) * 64 + d0);
                *(uint32_t*)dst = packh(c[mt][nt][0], c[mt][nt][1]);
                *(uint32_t*)(dst + 8 * 64) = packh(c[mt][nt][2], c[mt][nt][3]);
            }
        }
    } else if (QKV) {
        // Q/K: smem exchange + RoPE, fp16 out (Q pre-scaled 1/8)
        __syncthreads();
        float* ot = (float*)smem;
        {
#pragma unroll
            for (int mt = 0; mt < 2; mt++) {
                int ml = wm * 32 + mt * 16 + (lane >> 2);
#pragma unroll
                for (int nt = 0; nt < 4; nt++) {
                    int n = wn * 32 + nt * 8 + (lane & 3) * 2;
                    ot[ml * 132 + n]     = c[mt][nt][0];
                    ot[ml * 132 + n + 1] = c[mt][nt][1];
                    ot[(ml + 8) * 132 + n]     = c[mt][nt][2];
                    ot[(ml + 8) * 132 + n + 1] = c[mt][nt][3];
                }
            }
        }
        __syncthreads();
        {
            const int dq = (tid & 7) * 4;
            const float qs = (ws == 0) ? 0.125f : 1.f;
#pragma unroll
            for (int rp = 0; rp < 2; rp++) {
                int ml = (tid >> 3) + rp * 32;
                int mrow = m0 + ml;
                int b = mrow >> 11, s = mrow & (SEQ - 1);
                float4 cs4 = *(const float4*)&g_cos[s * 32 + dq];
                float4 sn4 = *(const float4*)&g_sin[s * 32 + dq];
                float csv[4] = {cs4.x, cs4.y, cs4.z, cs4.w};
                float snv[4] = {sn4.x, sn4.y, sn4.z, sn4.w};
#pragma unroll
                for (int hh2 = 0; hh2 < 2; hh2++) {
                    int h = nblk * 2 + hh2;
                    float r1[4], r2[4];
#pragma unroll
                    for (int i = 0; i < 4; i++) {
                        float v1 = ot[ml * 132 + hh2 * 64 + dq + i];
                        float v2 = ot[ml * 132 + hh2 * 64 + dq + 32 + i];
                        r1[i] = (v1 * csv[i] - v2 * snv[i]) * qs;
                        r2[i] = (v2 * csv[i] + v1 * snv[i]) * qs;
                    }
                    __half* kd = (__half*)Y + ((size_t)((b << 4) + h) * SEQ + s) * 64;
                    *(uint2*)(kd + dq)      = make_uint2(packh(r1[0], r1[1]), packh(r1[2], r1[3]));
                    *(uint2*)(kd + dq + 32) = make_uint2(packh(r2[0], r2[1]), packh(r2[2], r2[3]));
                }
            }
        }
    } else {
#pragma unroll
        for (int mt = 0; mt < 2; mt++) {
            int mrow = m0 + wm * 32 + mt * 16 + (lane >> 2);
#pragma unroll
            for (int nt = 0; nt < 4; nt++) {
                int n = nblk * 128 + wn * 32 + nt * 8 + (lane & 3) * 2;
                float* dst = Y + (size_t)mrow * 1024 + n;
                *(float2*)dst = make_float2(c[mt][nt][0], c[mt][nt][1]);
                *(float2*)(dst + 8 * 1024) = make_float2(c[mt][nt][2], c[mt][nt][3]);
            }
        }
    }
}

// ---------------------------------------------------------------------------
// Tensor-core flash attention (causal), balanced pairing, single-fp16 Q/K/V.
// Epilogue writes single fp16 to g_A16 [row][1024].
// ---------------------------------------------------------------------------
#define KROWB 144
#define QBYTES (128*KROWB)
#define KVB (64*KROWB)
#define ASTAGE (2*KVB)
#define ATT_SMEM (QBYTES + 2*ASTAGE)

__global__ __launch_bounds__(256, 2)
void attn_mma_kernel()
{
    extern __shared__ char smem[];
    const uint32_t sb = smem_u32(smem);
    const uint32_t Qs = sb;
    const uint32_t St0 = sb + QBYTES;

    const int bh = blockIdx.y;
    const int b = bh >> 4, h = bh & 15;

    const int tid = threadIdx.x;
    const int lane = tid & 31;
    const int w = tid >> 5;

    const char* Kg = (const char*)(g_Kc + (size_t)bh * SEQ * 64);
    const char* Vg = (const char*)(g_Vc + (size_t)bh * SEQ * 64);

    const uint32_t qLd = Qs + (w * 16 + (lane & 15)) * KROWB + (lane >> 4) * 16;
    const uint32_t kRow = ((lane >> 4) & 1) * 8 + (lane & 7);
    const uint32_t kCol = ((lane >> 3) & 1) * 16;
    const uint32_t vRow = ((lane >> 3) & 1) * 8 + (lane & 7);
    const uint32_t vCol = ((lane >> 4) & 1) * 16;

    const int g = lane >> 2;
    const int cq = (lane & 3) * 2;

#pragma unroll 1
    for (int task = 0; task < 2; task++) {
        const int qt = task ? (15 - blockIdx.x) : blockIdx.x;
        const int q0 = qt * 128;
        const char* Qg = (const char*)(g_Qc + ((size_t)bh * SEQ + q0) * 64);

        if (task) __syncthreads();

#pragma unroll
        for (int i = 0; i < 4; i++) {
            int idx = tid + i * 256;
            int r = idx >> 3, ch = (idx & 7) * 16;
            CP_ASYNC16(Qs + r * KROWB + ch, Qg + r * 128 + ch);
        }
#pragma unroll
        for (int i = 0; i < 4; i++) {
            int idx = tid + i * 256;
            if (idx < 512) {
                int r = idx >> 3, ch = (idx & 7) * 16;
                CP_ASYNC16(St0 + r * KROWB + ch, Kg + r * 128 + ch);
            } else {
                int j = idx - 512;
                int r = j >> 3, ch = (j & 7) * 16;
                CP_ASYNC16(St0 + KVB + r * KROWB + ch, Vg + r * 128 + ch);
            }
        }
        CP_COMMIT();

        float of[8][4];
#pragma unroll
        for (int i = 0; i < 8; i++)
#pragma unroll
            for (int q = 0; q < 4; q++) of[i][q] = 0.f;
        float m0r = -1e30f, m1r = -1e30f, l0r = 0.f, l1r = 0.f;
        uint32_t qh[4][4];

        const int wrow = q0 + w * 16;
        const int row0 = wrow + g;
        const int row1 = row0 + 8;

        const int nt = qt * 2 + 2;
        for (int t = 0; t < nt; t++) {
            if (t + 1 < nt) {
                const uint32_t stN = St0 + ((t + 1) & 1) * ASTAGE;
                const char* Kn = Kg + (size_t)(t + 1) * 64 * 128;
                const char* Vn = Vg + (size_t)(t + 1) * 64 * 128;
#pragma unroll
                for (int i = 0; i < 4; i++) {
                    int idx = tid + i * 256;
                    if (idx < 512) {
                        int r = idx >> 3, ch = (idx & 7) * 16;
                        CP_ASYNC16(stN + r * KROWB + ch, Kn + r * 128 + ch);
                    } else {
                        int j = idx - 512;
                        int r = j >> 3, ch = (j & 7) * 16;
                        CP_ASYNC16(stN + KVB + r * KROWB + ch, Vn + r * 128 + ch);
                    }
                }
            }
            CP_COMMIT();
            CP_WAIT1();
            __syncthreads();

            if (t == 0) {
#pragma unroll
                for (int ks = 0; ks < 4; ks++)
                    LDM_X4(qh[ks][0], qh[ks][1], qh[ks][2], qh[ks][3], qLd + ks * 32);
            }

            const int j0 = t * 64;
            if (j0 <= wrow + 15) {
                const uint32_t stK = St0 + (t & 1) * ASTAGE;
                const uint32_t stV = stK + KVB;
                const uint32_t kLd = stK + kRow * KROWB + kCol;
                const uint32_t vLd = stV + vRow * KROWB + vCol;

                float sc[8][4];
#pragma unroll
                for (int i = 0; i < 8; i++)
#pragma unroll
                    for (int q = 0; q < 4; q++) sc[i][q] = 0.f;

#pragma unroll
                for (int ks = 0; ks < 4; ks++) {
                    uint32_t bk[8][2];
#pragma unroll
                    for (int p = 0; p < 4; p++)
                        LDM_X4(bk[2*p][0], bk[2*p][1], bk[2*p+1][0], bk[2*p+1][1],
                               kLd + p * 16 * KROWB + ks * 32);
#pragma unroll
                    for (int nb = 0; nb < 8; nb++)
                        MMA16816(sc[nb], qh[ks], bk[nb]);
                }

                const bool domask = (j0 + 63 > wrow);
                if (domask) {
#pragma unroll
                    for (int nb = 0; nb < 8; nb++) {
                        int col = j0 + nb * 8 + cq;
                        if (col     > row0) sc[nb][0] = -1e30f;
                        if (col + 1 > row0) sc[nb][1] = -1e30f;
                        if (col     > row1) sc[nb][2] = -1e30f;
                        if (col + 1 > row1) sc[nb][3] = -1e30f;
                    }
                }

                float mx0 = -1e30f, mx1 = -1e30f;
#pragma unroll
                for (int nb = 0; nb < 8; nb++) {
                    mx0 = fmaxf(mx0, fmaxf(sc[nb][0], sc[nb][1]));
                    mx1 = fmaxf(mx1, fmaxf(sc[nb][2], sc[nb][3]));
                }
                mx0 = fmaxf(mx0, __shfl_xor_sync(0xffffffffu, mx0, 1));
                mx0 = fmaxf(mx0, __shfl_xor_sync(0xffffffffu, mx0, 2));
                mx1 = fmaxf(mx1, __shfl_xor_sync(0xffffffffu, mx1, 1));
                mx1 = fmaxf(mx1, __shfl_xor_sync(0xffffffffu, mx1, 2));

                float mn0 = fmaxf(m0r, mx0), mn1 = fmaxf(m1r, mx1);
                float al0 = __expf(m0r - mn0), al1 = __expf(m1r - mn1);
                m0r = mn0; m1r = mn1;

                float rs0 = 0.f, rs1 = 0.f;
#pragma unroll
                for (int nb = 0; nb < 8; nb++) {
                    sc[nb][0] = __expf(sc[nb][0] - mn0);
                    sc[nb][1] = __expf(sc[nb][1] - mn0);
                    sc[nb][2] = __expf(sc[nb][2] - mn1);
                    sc[nb][3] = __expf(sc[nb][3] - mn1);
                    rs0 += sc[nb][0] + sc[nb][1];
                    rs1 += sc[nb][2] + sc[nb][3];
                }
                rs0 += __shfl_xor_sync(0xffffffffu, rs0, 1);
                rs0 += __shfl_xor_sync(0xffffffffu, rs0, 2);
                rs1 += __shfl_xor_sync(0xffffffffu, rs1, 1);
                rs1 += __shfl_xor_sync(0xffffffffu, rs1, 2);
                l0r = l0r * al0 + rs0;
                l1r = l1r * al1 + rs1;

#pragma unroll
                for (int i = 0; i < 8; i++) {
                    of[i][0] *= al0; of[i][1] *= al0;
                    of[i][2] *= al1; of[i][3] *= al1;
                }

#pragma unroll
                for (int ks = 0; ks < 4; ks++) {
                    uint32_t aPh[4];
                    float* s0 = sc[2 * ks];
                    float* s1 = sc[2 * ks + 1];
                    aPh[0] = packh(s0[0], s0[1]);
                    aPh[1] = packh(s0[2], s0[3]);
                    aPh[2] = packh(s1[0], s1[1]);
                    aPh[3] = packh(s1[2], s1[3]);
#pragma unroll
                    for (int p = 0; p < 4; p++) {
                        uint32_t vh[4];
                        LDM_X4_T(vh[0], vh[1], vh[2], vh[3],
                                 vLd + ks * 16 * KROWB + p * 32);
                        MMA16816(of[2*p],     aPh, vh);
                        MMA16816(of[2*p + 1], aPh, vh + 2);
                    }
                }
            }
            __syncthreads();
        }

        // epilogue: single fp16 to g_A16 [row][1024]
        float inv0 = 1.f / l0r, inv1 = 1.f / l1r;
        __half* ar0 = g_A16 + ((size_t)(b * SEQ + row0)) * 1024 + h * 64;
        __half* ar1 = g_A16 + ((size_t)(b * SEQ + row1)) * 1024 + h * 64;
#pragma unroll
        for (int nb = 0; nb < 8; nb++) {
            int d = nb * 8 + cq;
            *(uint32_t*)(ar0 + d) = packh(of[nb][0] * inv0, of[nb][1] * inv0);
            *(uint32_t*)(ar1 + d) = packh(of[nb][2] * inv1, of[nb][3] * inv1);
        }
    }
}

// ---------------------------------------------------------------------------
// Launch
// ---------------------------------------------------------------------------
extern "C" void kernel_launch(void* const* d_in, const int* in_sizes, int n_in,
                              void* d_out, int out_size)
{
    const float* x  = (const float*)d_in[0];
    const float* Wq = (const float*)d_in[2];
    const float* Wk = (const float*)d_in[3];
    const float* Wv = (const float*)d_in[4];
    const float* Wo = (const float*)d_in[5];
    float* out = (float*)d_out;

    void *x16, *a16, *wq16, *wk16, *wv16, *wo16, *qc, *kc, *vc;
    cudaGetSymbolAddress(&x16, g_X16);
    cudaGetSymbolAddress(&a16, g_A16);
    cudaGetSymbolAddress(&wq16, g_Wq16);
    cudaGetSymbolAddress(&wk16, g_Wk16);
    cudaGetSymbolAddress(&wv16, g_Wv16);
    cudaGetSymbolAddress(&wo16, g_Wo16);
    cudaGetSymbolAddress(&qc, g_Qc);
    cudaGetSymbolAddress(&kc, g_Kc);
    cudaGetSymbolAddress(&vc, g_Vc);

    rope_table_kernel<<<(SEQ * 32 + 255) / 256, 256>>>();

    cvt16_kernel<<<(MTOT * 256 + 255) / 256, 256>>>(x, (__half*)x16, MTOT * 256);
    w16all_kernel<<<dim3(1024, 4), 256>>>(
        Wq, Wk, Wv, Wo,
        (__half*)wq16, (__half*)wk16, (__half*)wv16, (__half*)wo16);

    cudaFuncSetAttribute(hmma_gemm<1>, cudaFuncAttributeMaxDynamicSharedMemorySize, GSMEM);
    cudaFuncSetAttribute(hmma_gemm<0>, cudaFuncAttributeMaxDynamicSharedMemorySize, GSMEM);

    hmma_gemm<1><<<dim3(MTOT / 64, 24), 256, GSMEM>>>(
        (const __half*)x16, (const __half*)wq16,
        (const __half*)wk16, (const __half*)wv16,
        (float*)qc, (float*)kc, (float*)vc);

    cudaFuncSetAttribute(attn_mma_kernel,
                         cudaFuncAttributeMaxDynamicSharedMemorySize, ATT_SMEM);
    attn_mma_kernel<<<dim3(8, BH), 256, ATT_SMEM>>>();

    hmma_gemm<0><<<dim3(MTOT / 64, 8), 256, GSMEM>>>(
        (const __half*)a16, (const __half*)wo16,
        nullptr, nullptr, out, nullptr, nullptr);
}